// round 10
// baseline (speedup 1.0000x reference)
#include <cuda_runtime.h>
#include <cstdint>

#define BB   64
#define SS   2048
#define HH   256
#define G4   1024

// ---------------- scratch (device globals) -----------------------------------
__device__ float    g_h[2][16 * 1024];   // [buf][bg][k2*8 + b*2 + par]
__device__ unsigned g_flag[128 * 32];    // [(bg*8+hg)*32], 128B apart

// ---------------- f32x2 packed helpers (sm_103a) -----------------------------
__device__ __forceinline__ void ffma2(unsigned long long& d,
                                      unsigned long long a, unsigned long long b) {
    asm("fma.rn.f32x2 %0, %1, %2, %3;" : "=l"(d) : "l"(a), "l"(b), "l"(d));
}
__device__ __forceinline__ unsigned long long pack2(float x, float y) {
    unsigned long long r;
    asm("mov.b64 %0, {%1, %2};" : "=l"(r) : "f"(x), "f"(y));
    return r;
}
__device__ __forceinline__ void unpack2(unsigned long long v, float& a, float& b) {
    asm("mov.b64 {%0, %1}, %2;" : "=f"(a), "=f"(b) : "l"(v));
}
__device__ __forceinline__ float sum2(unsigned long long v) {
    float a, b; unpack2(v, a, b); return a + b;
}
__device__ __forceinline__ void fence_ar_gpu() {
    asm volatile("fence.acq_rel.gpu;" ::: "memory");
}

// ======================= init: zero flags each launch ========================
__global__ void init_flags_kernel() {
    g_flag[threadIdx.x * 32] = 0u;
}

// ======================= fused persistent LSTM ===============================
// 128 CTAs = 16 bg x 8 hg. W_hh in REGISTERS, W_ih in SMEM.
// Gates GEMM + lookahead x_proj (depth 2) fused per step; x_proj fills the
// issue slots that idle during the flag-wait. Sync = R9 (fence+atomic publish,
// volatile poll + fused h pull by warps 8..15).
#define GRID2 128
#define T2    512
#define LOOKA 2          // xp lookahead depth; ring has LOOKA+1 = 3 slots

__device__ __forceinline__ float sigm_f(float x) { return 1.f / (1.f + __expf(-x)); }
__device__ __forceinline__ float tanh_f(float x) { return 2.f / (1.f + __expf(-2.f * x)) - 1.f; }

// dynamic smem layout (floats):
//   Wi2   [128*128*2]   128KB  — W_ih slice as float2 [d2][r]
//   h2    [2*1024]        8KB  — hidden state, double buffered
//   redg  [4*512]         8KB  — gate partials [kq][r][b]
//   redx  [4*512]         8KB  — xp partials   [kq][r][b]
//   x_s   [1024]          4KB  — x slice for step t+LOOKA  [d2][b*2+par]
//   xp_s  [3*512]         6KB  — reduced xp ring
#define SM_WI    0
#define SM_H2    (2 * 128 * 128)
#define SM_REDG  (SM_H2 + 2 * 1024)
#define SM_REDX  (SM_REDG + 2048)
#define SM_XS    (SM_REDX + 2048)
#define SM_XPS   (SM_XS + 1024)
#define SM_TOTAL ((SM_XPS + 3 * 512) * 4)

__global__ __launch_bounds__(T2, 1)
void lstm_kernel(const float* __restrict__ W_hh, const float* __restrict__ W_ih,
                 const float* __restrict__ b_ih, const float* __restrict__ b_hh,
                 const float* __restrict__ x, float* __restrict__ out,
                 int write_state)
{
    extern __shared__ float sm[];
    float2* Wi2  = (float2*)&sm[SM_WI];
    float*  h2   = &sm[SM_H2];
    float*  redg = &sm[SM_REDG];
    float*  redx = &sm[SM_REDX];
    float*  x_s  = &sm[SM_XS];
    float*  xp_s = &sm[SM_XPS];

    const int tid   = threadIdx.x;
    const int r     = tid & 127;               // local gate row
    const int kq    = tid >> 7;                // k quarter (also: owns batch kq)
    const int lane  = tid & 31;
    const int wid   = tid >> 5;
    const int bg    = blockIdx.x >> 3;
    const int hg    = blockIdx.x & 7;
    const int bbase = bg * 4;
    const int jbase = hg * 32;
    const int row   = (r >> 5) * 256 + jbase + (r & 31);  // global weight row

    // ---- W_hh slice into registers: 32 f32x2 pairs over quarter kq ----
    unsigned long long w[32];
    {
        const float2* wp = (const float2*)&W_hh[(long)row * 256 + kq * 64];
#pragma unroll
        for (int i = 0; i < 32; i++) {
            float2 f = wp[i];
            w[i] = pack2(f.x, f.y);
        }
    }
    // ---- W_ih slice into smem: Wi2[d2][r], this thread covers its quarter ----
    {
        const float2* wp = (const float2*)&W_ih[(long)row * 256];
#pragma unroll 8
        for (int i = 0; i < 32; i++)
            Wi2[(kq * 32 + i) * 128 + r] = wp[kq * 32 + i];
    }
    const float breg = b_ih[row] + b_hh[row];

    unsigned* const my_flag = &g_flag[(bg * 8 + hg) * 32];

    // h(-1) = 0 in buffer 0
    *(float2*)&h2[tid * 2] = make_float2(0.f, 0.f);
    __syncthreads();

    // ---- warmup: compute xp(0), xp(1) into ring slots 0,1; stage x(2) ----
    for (int ws = 0; ws < LOOKA; ws++) {
        if (tid < 256) {
            const int b = tid >> 6, gq = tid & 63;
            float4 v = *(const float4*)&x[((long)(bbase + b) * SS + ws) * 256 + gq * 4];
            *(float2*)&x_s[(2 * gq) * 8 + b * 2]     = make_float2(v.x, v.y);
            *(float2*)&x_s[(2 * gq + 1) * 8 + b * 2] = make_float2(v.z, v.w);
        }
        __syncthreads();
        unsigned long long a0 = 0ull, a1 = 0ull, a2 = 0ull, a3 = 0ull;
        const float* xb = &x_s[kq * 256];
#pragma unroll
        for (int k2 = 0; k2 < 32; k2++) {
            unsigned long long wi = *(const unsigned long long*)&Wi2[(kq * 32 + k2) * 128 + r];
            ulonglong2 lo = *(const ulonglong2*)(xb + k2 * 8);
            ulonglong2 hi = *(const ulonglong2*)(xb + k2 * 8 + 4);
            ffma2(a0, wi, lo.x); ffma2(a1, wi, lo.y);
            ffma2(a2, wi, hi.x); ffma2(a3, wi, hi.y);
        }
        *(float4*)&redx[kq * 512 + r * 4] =
            make_float4(sum2(a0), sum2(a1), sum2(a2), sum2(a3));
        __syncthreads();
        xp_s[ws * 512 + tid] = breg +
            (redx[0 * 512 + r * 4 + kq] + redx[1 * 512 + r * 4 + kq]) +
            (redx[2 * 512 + r * 4 + kq] + redx[3 * 512 + r * 4 + kq]);
        __syncthreads();
    }
    if (tid < 256) {
        const int b = tid >> 6, gq = tid & 63;
        float4 v = *(const float4*)&x[((long)(bbase + b) * SS + LOOKA) * 256 + gq * 4];
        *(float2*)&x_s[(2 * gq) * 8 + b * 2]     = make_float2(v.x, v.y);
        *(float2*)&x_s[(2 * gq + 1) * 8 + b * 2] = make_float2(v.z, v.w);
    }
    __syncthreads();

    float c_reg = 0.f, h_last = 0.f;

    for (int t = 0; t < SS; t++) {
        const int p = t & 1;
        const float xp = xp_s[(t % 3) * 512 + tid];   // this step's x_proj share
        const bool do_x = (t + LOOKA < SS);

        // ---- gates k-loop: W_hh regs x h2[p] (broadcast), packed parity ----
        {
            unsigned long long a0 = 0ull, a1 = 0ull, a2 = 0ull, a3 = 0ull;
            const float* hb = &h2[p * 1024 + kq * 256];
#pragma unroll
            for (int k2 = 0; k2 < 32; k2++) {
                ulonglong2 lo = *(const ulonglong2*)(hb + k2 * 8);
                ulonglong2 hi = *(const ulonglong2*)(hb + k2 * 8 + 4);
                ffma2(a0, w[k2], lo.x); ffma2(a1, w[k2], lo.y);
                ffma2(a2, w[k2], hi.x); ffma2(a3, w[k2], hi.y);
            }
            float4 part = make_float4(sum2(a0), sum2(a1), sum2(a2), sum2(a3));
            ((float*)&part)[kq] += xp;
            *(float4*)&redg[kq * 512 + r * 4] = part;
        }

        // ---- xp(t+LOOKA) k-loop: W_ih smem x x_s (broadcast) ----
        if (do_x) {
            unsigned long long a0 = 0ull, a1 = 0ull, a2 = 0ull, a3 = 0ull;
            const float* xb = &x_s[kq * 256];
#pragma unroll
            for (int k2 = 0; k2 < 32; k2++) {
                unsigned long long wi = *(const unsigned long long*)&Wi2[(kq * 32 + k2) * 128 + r];
                ulonglong2 lo = *(const ulonglong2*)(xb + k2 * 8);
                ulonglong2 hi = *(const ulonglong2*)(xb + k2 * 8 + 4);
                ffma2(a0, wi, lo.x); ffma2(a1, wi, lo.y);
                ffma2(a2, wi, hi.x); ffma2(a3, wi, hi.y);
            }
            *(float4*)&redx[kq * 512 + r * 4] =
                make_float4(sum2(a0), sum2(a1), sum2(a2), sum2(a3));
        }
        __syncthreads();                                   // sync A

        // ---- gather xp(t+LOOKA) -> ring (all threads) ----
        if (do_x) {
            xp_s[((t + LOOKA) % 3) * 512 + tid] = breg +
                (redx[0 * 512 + r * 4 + kq] + redx[1 * 512 + r * 4 + kq]) +
                (redx[2 * 512 + r * 4 + kq] + redx[3 * 512 + r * 4 + kq]);
        }

        // ---- gather gates + elementwise: thread (b = tid>>5, j = tid&31) ----
        float hn = 0.f;
        if (tid < 128) {
            const int b = tid >> 5, j = tid & 31;
            float g[4];
#pragma unroll
            for (int gi = 0; gi < 4; gi++) {
                const int lr = gi * 32 + j;
                g[gi] = (redg[0 * 512 + lr * 4 + b] + redg[1 * 512 + lr * 4 + b]) +
                        (redg[2 * 512 + lr * 4 + b] + redg[3 * 512 + lr * 4 + b]);
            }
            float iv = sigm_f(g[0]);
            float fv = sigm_f(g[1]);
            float gv = tanh_f(g[2]);
            float ov = sigm_f(g[3]);
            c_reg = fv * c_reg + iv * gv;
            hn = ov * tanh_f(c_reg);
            h_last = hn;
            const int kh = jbase + j;
            g_h[p ^ 1][bg * 1024 + (kh >> 1) * 8 + b * 2 + (kh & 1)] = hn;
        }
        __syncthreads();                                   // sync B: h stores done

        // ---- publish own flag (R9 fast path) ----
        if (tid == 0 && t + 1 < SS) {
            fence_ar_gpu();
            atomicAdd(my_flag, 1u);
        }

        // ---- warps 0-7: out store + stage x(t+1+LOOKA) during poll shadow ----
        if (tid < 128) {
            const int b = tid >> 5, j = tid & 31;
            out[(((long)(bbase + b)) * SS + t) * HH + jbase + j] = hn;
        }
        if (t + 1 + LOOKA < SS && tid < 256) {
            const int b = tid >> 6, gq = tid & 63;
            float4 v = *(const float4*)
                &x[((long)(bbase + b) * SS + (t + 1 + LOOKA)) * 256 + gq * 4];
            *(float2*)&x_s[(2 * gq) * 8 + b * 2]     = make_float2(v.x, v.y);
            *(float2*)&x_s[(2 * gq + 1) * 8 + b * 2] = make_float2(v.z, v.w);
        }

        // ---- warps 8-15: poll peer flag, pull its h chunk into h2[p^1] ----
        if (t + 1 < SS && wid >= 8) {
            const int peer = wid - 8;
            if (lane == 0) {
                const unsigned* fp = &g_flag[(bg * 8 + peer) * 32];
                while (*((volatile unsigned*)fp) < (unsigned)(t + 1)) { }
            }
            __syncwarp();
            float4 hv = __ldcg((const float4*)
                &g_h[p ^ 1][bg * 1024 + peer * 128 + lane * 4]);
            *(float4*)&h2[(p ^ 1) * 1024 + peer * 128 + lane * 4] = hv;
        }
        __syncthreads();                                   // sync C
    }

    if (write_state && tid < 128) {
        const int b = tid >> 5, j = tid & 31;
        const long hoff = (long)BB * SS * HH;
        out[hoff +           (bbase + b) * HH + jbase + j] = h_last;
        out[hoff + BB * HH + (bbase + b) * HH + jbase + j] = c_reg;
    }
}

// ============================= launch ========================================
extern "C" void kernel_launch(void* const* d_in, const int* in_sizes, int n_in,
                              void* d_out, int out_size)
{
    const float* x    = (const float*)d_in[0];
    const float* W_ih = (const float*)d_in[1];
    const float* W_hh = (const float*)d_in[2];
    const float* b_ih = (const float*)d_in[3];
    const float* b_hh = (const float*)d_in[4];
    float* out = (float*)d_out;

    init_flags_kernel<<<1, 128>>>();

    cudaFuncSetAttribute(lstm_kernel,
                         cudaFuncAttributeMaxDynamicSharedMemorySize, SM_TOTAL);
    const long full = (long)BB * SS * HH + 2L * BB * HH;
    int write_state = ((long)out_size >= full) ? 1 : 0;
    lstm_kernel<<<GRID2, T2, SM_TOTAL>>>(W_hh, W_ih, b_ih, b_hh, x, out,
                                         write_state);
}

// round 12
// speedup vs baseline: 1.1556x; 1.1556x over previous
#include <cuda_runtime.h>
#include <cstdint>

#define BB   64
#define SS   2048
#define HH   256
#define G4   1024

// ---------------- scratch (device globals) -----------------------------------
__device__ float    g_h[2][16 * 1024];   // [buf][bg][k2*8 + b*2 + par]
__device__ unsigned g_flag[128 * 32];    // [(bg*8+hg)*32], 128B apart

// ---------------- f32x2 packed helpers (sm_103a) -----------------------------
__device__ __forceinline__ void ffma2(unsigned long long& d,
                                      unsigned long long a, unsigned long long b) {
    asm("fma.rn.f32x2 %0, %1, %2, %3;" : "=l"(d) : "l"(a), "l"(b), "l"(d));
}
__device__ __forceinline__ unsigned long long pack2(float x, float y) {
    unsigned long long r;
    asm("mov.b64 %0, {%1, %2};" : "=l"(r) : "f"(x), "f"(y));
    return r;
}
__device__ __forceinline__ void unpack2(unsigned long long v, float& a, float& b) {
    asm("mov.b64 {%0, %1}, %2;" : "=f"(a), "=f"(b) : "l"(v));
}
__device__ __forceinline__ float sum2(unsigned long long v) {
    float a, b; unpack2(v, a, b); return a + b;
}
__device__ __forceinline__ void fence_ar_gpu() {
    asm volatile("fence.acq_rel.gpu;" ::: "memory");
}

// ======================= init: zero flags each launch ========================
__global__ void init_flags_kernel() {
    g_flag[threadIdx.x * 32] = 0u;
}

// ======================= fused persistent LSTM ===============================
// 128 CTAs = 16 bg x 8 hg. W_hh in REGISTERS, W_ih in SMEM.
// Per step: gates GEMM on the critical path; xp(t+2) GEMM + x staging + out
// store all placed in the flag-wait window (after publish, before poll).
#define GRID2 128
#define T2    512
#define LOOKA 2          // xp lookahead depth; ring has 3 slots

__device__ __forceinline__ float sigm_f(float x) { return 1.f / (1.f + __expf(-x)); }
__device__ __forceinline__ float tanh_f(float x) { return 2.f / (1.f + __expf(-2.f * x)) - 1.f; }

// dynamic smem layout (floats):
//   Wi2   [128*128*2]   128KB  — W_ih slice as float2 [d2][r]
//   h2    [2*1024]        8KB  — hidden state, double buffered
//   redg  [4*512]         8KB  — gate partials [kq][r][b]
//   redx  [4*512]         8KB  — xp partials   [kq][r][b]
//   x_s   [2*1024]        8KB  — x slices, double buffered [buf][d2][b*2+par]
//   xp_s  [3*512]         6KB  — reduced xp ring
#define SM_WI    0
#define SM_H2    (2 * 128 * 128)
#define SM_REDG  (SM_H2 + 2 * 1024)
#define SM_REDX  (SM_REDG + 2048)
#define SM_XS    (SM_REDX + 2048)
#define SM_XPS   (SM_XS + 2 * 1024)
#define SM_TOTAL ((SM_XPS + 3 * 512) * 4)

__global__ __launch_bounds__(T2, 1)
void lstm_kernel(const float* __restrict__ W_hh, const float* __restrict__ W_ih,
                 const float* __restrict__ b_ih, const float* __restrict__ b_hh,
                 const float* __restrict__ x, float* __restrict__ out,
                 int write_state)
{
    extern __shared__ float sm[];
    float2* Wi2  = (float2*)&sm[SM_WI];
    float*  h2   = &sm[SM_H2];
    float*  redg = &sm[SM_REDG];
    float*  redx = &sm[SM_REDX];
    float*  x_s  = &sm[SM_XS];
    float*  xp_s = &sm[SM_XPS];

    const int tid   = threadIdx.x;
    const int r     = tid & 127;               // local gate row
    const int kq    = tid >> 7;                // k quarter (owns batch kq's xp)
    const int lane  = tid & 31;
    const int wid   = tid >> 5;
    const int bg    = blockIdx.x >> 3;
    const int hg    = blockIdx.x & 7;
    const int bbase = bg * 4;
    const int jbase = hg * 32;
    const int row   = (r >> 5) * 256 + jbase + (r & 31);  // global weight row

    // ---- W_hh slice into registers: 32 f32x2 pairs over quarter kq ----
    unsigned long long w[32];
    {
        const float2* wp = (const float2*)&W_hh[(long)row * 256 + kq * 64];
#pragma unroll
        for (int i = 0; i < 32; i++) {
            float2 f = wp[i];
            w[i] = pack2(f.x, f.y);
        }
    }
    // ---- W_ih slice into smem: Wi2[d2][r], this thread covers its quarter ----
    {
        const float2* wp = (const float2*)&W_ih[(long)row * 256];
#pragma unroll 8
        for (int i = 0; i < 32; i++)
            Wi2[(kq * 32 + i) * 128 + r] = wp[kq * 32 + i];
    }
    const float breg = b_ih[row] + b_hh[row];

    unsigned* const my_flag = &g_flag[(bg * 8 + hg) * 32];

    // h(-1) = 0 in buffer 0
    *(float2*)&h2[tid * 2] = make_float2(0.f, 0.f);
    __syncthreads();

    // ---- warmup: xp(0), xp(1) into ring slots 0,1; then stage x(2) ----
    for (int ws = 0; ws < LOOKA; ws++) {
        if (tid < 256) {
            const int b = tid >> 6, gq = tid & 63;
            float4 v = *(const float4*)&x[((long)(bbase + b) * SS + ws) * 256 + gq * 4];
            float* xb = &x_s[(ws & 1) * 1024];
            *(float2*)&xb[(2 * gq) * 8 + b * 2]     = make_float2(v.x, v.y);
            *(float2*)&xb[(2 * gq + 1) * 8 + b * 2] = make_float2(v.z, v.w);
        }
        __syncthreads();
        unsigned long long a0 = 0ull, a1 = 0ull, a2 = 0ull, a3 = 0ull;
        const float* xb = &x_s[(ws & 1) * 1024 + kq * 256];
#pragma unroll
        for (int k2 = 0; k2 < 32; k2++) {
            unsigned long long wi = *(const unsigned long long*)&Wi2[(kq * 32 + k2) * 128 + r];
            ulonglong2 lo = *(const ulonglong2*)(xb + k2 * 8);
            ulonglong2 hi = *(const ulonglong2*)(xb + k2 * 8 + 4);
            ffma2(a0, wi, lo.x); ffma2(a1, wi, lo.y);
            ffma2(a2, wi, hi.x); ffma2(a3, wi, hi.y);
        }
        *(float4*)&redx[kq * 512 + r * 4] =
            make_float4(sum2(a0), sum2(a1), sum2(a2), sum2(a3));
        __syncthreads();
        xp_s[ws * 512 + tid] = breg +
            (redx[0 * 512 + r * 4 + kq] + redx[1 * 512 + r * 4 + kq]) +
            (redx[2 * 512 + r * 4 + kq] + redx[3 * 512 + r * 4 + kq]);
        __syncthreads();
    }
    if (tid < 256) {   // stage x(2) into buffer 0 (step 0 reads buf t&1 = 0)
        const int b = tid >> 6, gq = tid & 63;
        float4 v = *(const float4*)&x[((long)(bbase + b) * SS + LOOKA) * 256 + gq * 4];
        float* xb = &x_s[0];
        *(float2*)&xb[(2 * gq) * 8 + b * 2]     = make_float2(v.x, v.y);
        *(float2*)&xb[(2 * gq + 1) * 8 + b * 2] = make_float2(v.z, v.w);
    }
    __syncthreads();

    float c_reg = 0.f, h_last = 0.f;

    for (int t = 0; t < SS; t++) {
        const int p = t & 1;
        const float xp = xp_s[(t % 3) * 512 + tid];
        const bool do_x = (t + LOOKA < SS);

        // ---- gates k-loop: W_hh regs x h2[p] (broadcast), packed parity ----
        {
            unsigned long long a0 = 0ull, a1 = 0ull, a2 = 0ull, a3 = 0ull;
            const float* hb = &h2[p * 1024 + kq * 256];
#pragma unroll
            for (int k2 = 0; k2 < 32; k2++) {
                ulonglong2 lo = *(const ulonglong2*)(hb + k2 * 8);
                ulonglong2 hi = *(const ulonglong2*)(hb + k2 * 8 + 4);
                ffma2(a0, w[k2], lo.x); ffma2(a1, w[k2], lo.y);
                ffma2(a2, w[k2], hi.x); ffma2(a3, w[k2], hi.y);
            }
            float4 part = make_float4(sum2(a0), sum2(a1), sum2(a2), sum2(a3));
            ((float*)&part)[kq] += xp;
            *(float4*)&redg[kq * 512 + r * 4] = part;
        }
        __syncthreads();                                   // sync A

        // ---- gather gates + elementwise: thread (b = tid>>5, j = tid&31) ----
        float hn = 0.f;
        if (tid < 128) {
            const int b = tid >> 5, j = tid & 31;
            float g[4];
#pragma unroll
            for (int gi = 0; gi < 4; gi++) {
                const int lr = gi * 32 + j;
                g[gi] = (redg[0 * 512 + lr * 4 + b] + redg[1 * 512 + lr * 4 + b]) +
                        (redg[2 * 512 + lr * 4 + b] + redg[3 * 512 + lr * 4 + b]);
            }
            float iv = sigm_f(g[0]);
            float fv = sigm_f(g[1]);
            float gv = tanh_f(g[2]);
            float ov = sigm_f(g[3]);
            c_reg = fv * c_reg + iv * gv;
            hn = ov * tanh_f(c_reg);
            h_last = hn;
            const int kh = jbase + j;
            g_h[p ^ 1][bg * 1024 + (kh >> 1) * 8 + b * 2 + (kh & 1)] = hn;
        }
        __syncthreads();                                   // sync B: h stores done

        // ---- publish own flag (R9 fast path) ----
        if (tid == 0 && t + 1 < SS) {
            fence_ar_gpu();
            atomicAdd(my_flag, 1u);
        }

        // ================= WAIT WINDOW (all latency hidden here) =============
        // warps 0-3: out store
        if (tid < 128) {
            const int b = tid >> 5, j = tid & 31;
            out[(((long)(bbase + b)) * SS + t) * HH + jbase + j] = hn;
        }

        // all warps: xp(t+LOOKA) k-loop (warps 8-15 run it BEFORE polling,
        // giving peer flags time to propagate)
        if (do_x) {
            unsigned long long a0 = 0ull, a1 = 0ull, a2 = 0ull, a3 = 0ull;
            const float* xb = &x_s[(t & 1) * 1024 + kq * 256];
#pragma unroll
            for (int k2 = 0; k2 < 32; k2++) {
                unsigned long long wi = *(const unsigned long long*)&Wi2[(kq * 32 + k2) * 128 + r];
                ulonglong2 lo = *(const ulonglong2*)(xb + k2 * 8);
                ulonglong2 hi = *(const ulonglong2*)(xb + k2 * 8 + 4);
                ffma2(a0, wi, lo.x); ffma2(a1, wi, lo.y);
                ffma2(a2, wi, hi.x); ffma2(a3, wi, hi.y);
            }
            *(float4*)&redx[kq * 512 + r * 4] =
                make_float4(sum2(a0), sum2(a1), sum2(a2), sum2(a3));
        }

        // warps 0-7: stage x(t+1+LOOKA) into the other x buffer
        if (t + 1 + LOOKA < SS && tid < 256) {
            const int b = tid >> 6, gq = tid & 63;
            float4 v = *(const float4*)
                &x[((long)(bbase + b) * SS + (t + 1 + LOOKA)) * 256 + gq * 4];
            float* xb = &x_s[((t + 1) & 1) * 1024];
            *(float2*)&xb[(2 * gq) * 8 + b * 2]     = make_float2(v.x, v.y);
            *(float2*)&xb[(2 * gq + 1) * 8 + b * 2] = make_float2(v.z, v.w);
        }

        // warps 8-15: poll peer flag, pull its h chunk into h2[p^1]
        if (t + 1 < SS && wid >= 8) {
            const int peer = wid - 8;
            if (lane == 0) {
                const unsigned* fp = &g_flag[(bg * 8 + peer) * 32];
                while (*((volatile unsigned*)fp) < (unsigned)(t + 1)) {
                    __nanosleep(32);
                }
            }
            __syncwarp();
            float4 hv = __ldcg((const float4*)
                &g_h[p ^ 1][bg * 1024 + peer * 128 + lane * 4]);
            *(float4*)&h2[(p ^ 1) * 1024 + peer * 128 + lane * 4] = hv;
        }
        __syncthreads();                                   // sync C

        // ---- gather xp(t+LOOKA) -> ring (ordered vs next redx by sync A) ----
        if (do_x) {
            xp_s[((t + LOOKA) % 3) * 512 + tid] = breg +
                (redx[0 * 512 + r * 4 + kq] + redx[1 * 512 + r * 4 + kq]) +
                (redx[2 * 512 + r * 4 + kq] + redx[3 * 512 + r * 4 + kq]);
        }
    }

    if (write_state && tid < 128) {
        const int b = tid >> 5, j = tid & 31;
        const long hoff = (long)BB * SS * HH;
        out[hoff +           (bbase + b) * HH + jbase + j] = h_last;
        out[hoff + BB * HH + (bbase + b) * HH + jbase + j] = c_reg;
    }
}

// ============================= launch ========================================
extern "C" void kernel_launch(void* const* d_in, const int* in_sizes, int n_in,
                              void* d_out, int out_size)
{
    const float* x    = (const float*)d_in[0];
    const float* W_ih = (const float*)d_in[1];
    const float* W_hh = (const float*)d_in[2];
    const float* b_ih = (const float*)d_in[3];
    const float* b_hh = (const float*)d_in[4];
    float* out = (float*)d_out;

    init_flags_kernel<<<1, 128>>>();

    cudaFuncSetAttribute(lstm_kernel,
                         cudaFuncAttributeMaxDynamicSharedMemorySize, SM_TOTAL);
    const long full = (long)BB * SS * HH + 2L * BB * HH;
    int write_state = ((long)out_size >= full) ? 1 : 0;
    lstm_kernel<<<GRID2, T2, SM_TOTAL>>>(W_hh, W_ih, b_ih, b_hh, x, out,
                                         write_state);
}

// round 13
// speedup vs baseline: 1.3802x; 1.1944x over previous
#include <cuda_runtime.h>
#include <cstdint>

#define BB   64
#define SS   2048
#define HH   256
#define G4   1024

// ---------------- scratch (device globals) -----------------------------------
__device__ float    g_h[2][16 * 1024];   // [buf][bg][k2*8 + b*2 + par]
__device__ unsigned g_flag[128 * 32];    // [(bg*8+hg)*32], 128B apart

// ---------------- f32x2 packed helpers (sm_103a) -----------------------------
__device__ __forceinline__ void ffma2(unsigned long long& d,
                                      unsigned long long a, unsigned long long b) {
    asm("fma.rn.f32x2 %0, %1, %2, %3;" : "=l"(d) : "l"(a), "l"(b), "l"(d));
}
__device__ __forceinline__ unsigned long long pack2(float x, float y) {
    unsigned long long r;
    asm("mov.b64 %0, {%1, %2};" : "=l"(r) : "f"(x), "f"(y));
    return r;
}
__device__ __forceinline__ void unpack2(unsigned long long v, float& a, float& b) {
    asm("mov.b64 {%0, %1}, %2;" : "=f"(a), "=f"(b) : "l"(v));
}
__device__ __forceinline__ float sum2(unsigned long long v) {
    float a, b; unpack2(v, a, b); return a + b;
}
__device__ __forceinline__ void fence_ar_gpu() {
    asm volatile("fence.acq_rel.gpu;" ::: "memory");
}
__device__ __forceinline__ uint32_t smem_u32(const void* p) {
    uint32_t a;
    asm("{ .reg .u64 t; cvta.to.shared.u64 t, %1; cvt.u32.u64 %0, t; }"
        : "=r"(a) : "l"(p));
    return a;
}
__device__ __forceinline__ void cp_async16(uint32_t dst, const void* src) {
    asm volatile("cp.async.cg.shared.global [%0], [%1], 16;"
                 :: "r"(dst), "l"(src) : "memory");
}
__device__ __forceinline__ void cp_async_wait_all() {
    asm volatile("cp.async.commit_group;\n\tcp.async.wait_group 0;" ::: "memory");
}

// ======================= init: zero flags each launch ========================
__global__ void init_flags_kernel() {
    g_flag[threadIdx.x * 32] = 0u;
}

// ======================= fused persistent LSTM ===============================
// 128 CTAs = 16 bg x 8 hg. W_hh in REGISTERS, W_ih in SMEM.
// Window roles (concurrent): warps 0-3 EW+publish+x-stage, warps 4-7 full
// xp(t+2) GEMM, warps 8-15 poll+cp.async h pull. Chain = max, not sum.
#define GRID2 128
#define T2    512
#define LOOKA 2

__device__ __forceinline__ float sigm_f(float x) { return 1.f / (1.f + __expf(-x)); }
__device__ __forceinline__ float tanh_f(float x) { return 2.f / (1.f + __expf(-2.f * x)) - 1.f; }

// dynamic smem (floats):
//   Wi2  [128*128*2]  128KB   W_ih slice as float2 [d2][r]
//   h2   [2*1024]       8KB   hidden, double buffered
//   redg [4*512]        8KB   gate partials [kq][r][b]
//   redx [512]          2KB   xp results [r][b] (no reduction needed)
//   x_s  [2*1024]       8KB   x slices, double buffered
#define SM_WI    0
#define SM_H2    (2 * 128 * 128)
#define SM_REDG  (SM_H2 + 2 * 1024)
#define SM_REDX  (SM_REDG + 2048)
#define SM_XS    (SM_REDX + 512)
#define SM_TOTAL ((SM_XS + 2 * 1024) * 4)

__global__ __launch_bounds__(T2, 1)
void lstm_kernel(const float* __restrict__ W_hh, const float* __restrict__ W_ih,
                 const float* __restrict__ b_ih, const float* __restrict__ b_hh,
                 const float* __restrict__ x, float* __restrict__ out,
                 int write_state)
{
    extern __shared__ float sm[];
    float2* Wi2  = (float2*)&sm[SM_WI];
    float*  h2   = &sm[SM_H2];
    float*  redg = &sm[SM_REDG];
    float*  redx = &sm[SM_REDX];
    float*  x_s  = &sm[SM_XS];

    const int tid   = threadIdx.x;
    const int r     = tid & 127;               // local gate row
    const int kq    = tid >> 7;                // k quarter (owns batch kq's xp)
    const int lane  = tid & 31;
    const int wid   = tid >> 5;
    const int bg    = blockIdx.x >> 3;
    const int hg    = blockIdx.x & 7;
    const int bbase = bg * 4;
    const int jbase = hg * 32;
    const int row   = (r >> 5) * 256 + jbase + (r & 31);  // global weight row

    // ---- W_hh slice into registers: 32 f32x2 pairs over quarter kq ----
    unsigned long long w[32];
    {
        const float2* wp = (const float2*)&W_hh[(long)row * 256 + kq * 64];
#pragma unroll
        for (int i = 0; i < 32; i++) {
            float2 f = wp[i];
            w[i] = pack2(f.x, f.y);
        }
    }
    // ---- W_ih slice into smem: Wi2[d2][r] ----
    {
        const float2* wp = (const float2*)&W_ih[(long)row * 256];
#pragma unroll 8
        for (int i = 0; i < 32; i++)
            Wi2[(kq * 32 + i) * 128 + r] = wp[kq * 32 + i];
    }
    const float breg = b_ih[row] + b_hh[row];

    unsigned* const my_flag = &g_flag[(bg * 8 + hg) * 32];
    const uint32_t h2_a = smem_u32(&h2[0]);

    // h(-1) = 0 in buffer 0
    *(float2*)&h2[tid * 2] = make_float2(0.f, 0.f);
    __syncthreads();

    // ================= warmup: xp(0), xp(1) into regs; stage x(2) ============
    float xp0 = 0.f, xp1 = 0.f;
#pragma unroll
    for (int ws = 0; ws < LOOKA; ws++) {
        if (tid < 128) {   // stage x(ws) into buf ws&1
#pragma unroll
            for (int half = 0; half < 2; half++) {
                int u = tid + half * 128;
                int b = u >> 6, gq = u & 63;
                float4 v = *(const float4*)&x[((long)(bbase + b) * SS + ws) * 256 + gq * 4];
                float* xb = &x_s[(ws & 1) * 1024];
                *(float2*)&xb[(2 * gq) * 8 + b * 2]     = make_float2(v.x, v.y);
                *(float2*)&xb[(2 * gq + 1) * 8 + b * 2] = make_float2(v.z, v.w);
            }
        }
        __syncthreads();
        if (wid >= 4 && wid < 8) {   // full-k xp GEMM, thread = row tid-128
            const int rr = tid - 128;
            unsigned long long a0 = 0ull, a1 = 0ull, a2 = 0ull, a3 = 0ull;
            const float* xb = &x_s[(ws & 1) * 1024];
#pragma unroll 16
            for (int k2 = 0; k2 < 128; k2++) {
                unsigned long long wi = *(const unsigned long long*)&Wi2[k2 * 128 + rr];
                ulonglong2 lo = *(const ulonglong2*)(xb + k2 * 8);
                ulonglong2 hi = *(const ulonglong2*)(xb + k2 * 8 + 4);
                ffma2(a0, wi, lo.x); ffma2(a1, wi, lo.y);
                ffma2(a2, wi, hi.x); ffma2(a3, wi, hi.y);
            }
            *(float4*)&redx[rr * 4] = make_float4(sum2(a0), sum2(a1), sum2(a2), sum2(a3));
        }
        __syncthreads();
        float nv = breg + redx[r * 4 + kq];
        if (ws == 0) xp0 = nv; else xp1 = nv;
        __syncthreads();   // redx reads done before next overwrite
    }
    if (tid < 128) {   // stage x(2) into buf 0 (step 0 window reads buf t&1=0)
#pragma unroll
        for (int half = 0; half < 2; half++) {
            int u = tid + half * 128;
            int b = u >> 6, gq = u & 63;
            float4 v = *(const float4*)&x[((long)(bbase + b) * SS + LOOKA) * 256 + gq * 4];
            float* xb = &x_s[0];
            *(float2*)&xb[(2 * gq) * 8 + b * 2]     = make_float2(v.x, v.y);
            *(float2*)&xb[(2 * gq + 1) * 8 + b * 2] = make_float2(v.z, v.w);
        }
    }
    __syncthreads();

    float c_reg = 0.f, h_last = 0.f;

    for (int t = 0; t < SS; t++) {
        const int p = t & 1;
        const float xp = xp0;
        const bool do_x = (t + LOOKA < SS);

        // ---- gates k-loop: W_hh regs x h2[p] (broadcast), packed parity ----
        {
            unsigned long long a0 = 0ull, a1 = 0ull, a2 = 0ull, a3 = 0ull;
            const float* hb = &h2[p * 1024 + kq * 256];
#pragma unroll
            for (int k2 = 0; k2 < 32; k2++) {
                ulonglong2 lo = *(const ulonglong2*)(hb + k2 * 8);
                ulonglong2 hi = *(const ulonglong2*)(hb + k2 * 8 + 4);
                ffma2(a0, w[k2], lo.x); ffma2(a1, w[k2], lo.y);
                ffma2(a2, w[k2], hi.x); ffma2(a3, w[k2], hi.y);
            }
            float4 part = make_float4(sum2(a0), sum2(a1), sum2(a2), sum2(a3));
            ((float*)&part)[kq] += xp;
            *(float4*)&redg[kq * 512 + r * 4] = part;
        }
        __syncthreads();                                   // sync A

        // ============== WINDOW: three concurrent warp roles ==================
        // ---- warps 0-3: gather + EW + h/out store + publish + x stage ----
        if (tid < 128) {
            const int b = tid >> 5, j = tid & 31;
            float g[4];
#pragma unroll
            for (int gi = 0; gi < 4; gi++) {
                const int lr = gi * 32 + j;
                g[gi] = (redg[0 * 512 + lr * 4 + b] + redg[1 * 512 + lr * 4 + b]) +
                        (redg[2 * 512 + lr * 4 + b] + redg[3 * 512 + lr * 4 + b]);
            }
            float iv = sigm_f(g[0]);
            float fv = sigm_f(g[1]);
            float gv = tanh_f(g[2]);
            float ov = sigm_f(g[3]);
            c_reg = fv * c_reg + iv * gv;
            float hn = ov * tanh_f(c_reg);
            h_last = hn;
            const int kh = jbase + j;
            g_h[p ^ 1][bg * 1024 + (kh >> 1) * 8 + b * 2 + (kh & 1)] = hn;
            out[(((long)(bbase + b)) * SS + t) * HH + jbase + j] = hn;
            asm volatile("bar.sync 7, 128;" ::: "memory");   // h stores visible
            if (tid == 0 && t + 1 < SS) {
                fence_ar_gpu();
                atomicAdd(my_flag, 1u);
            }
            // stage x(t+1+LOOKA) into the other buffer
            if (t + 1 + LOOKA < SS) {
#pragma unroll
                for (int half = 0; half < 2; half++) {
                    int u = tid + half * 128;
                    int b2 = u >> 6, gq = u & 63;
                    float4 v = *(const float4*)
                        &x[((long)(bbase + b2) * SS + (t + 1 + LOOKA)) * 256 + gq * 4];
                    float* xb = &x_s[((t + 1) & 1) * 1024];
                    *(float2*)&xb[(2 * gq) * 8 + b2 * 2]     = make_float2(v.x, v.y);
                    *(float2*)&xb[(2 * gq + 1) * 8 + b2 * 2] = make_float2(v.z, v.w);
                }
            }
        }

        // ---- warps 4-7: full-k xp(t+LOOKA) GEMM (thread = one row) ----
        if (do_x && wid >= 4 && wid < 8) {
            const int rr = tid - 128;
            unsigned long long a0 = 0ull, a1 = 0ull, a2 = 0ull, a3 = 0ull;
            const float* xb = &x_s[(t & 1) * 1024];
#pragma unroll 16
            for (int k2 = 0; k2 < 128; k2++) {
                unsigned long long wi = *(const unsigned long long*)&Wi2[k2 * 128 + rr];
                ulonglong2 lo = *(const ulonglong2*)(xb + k2 * 8);
                ulonglong2 hi = *(const ulonglong2*)(xb + k2 * 8 + 4);
                ffma2(a0, wi, lo.x); ffma2(a1, wi, lo.y);
                ffma2(a2, wi, hi.x); ffma2(a3, wi, hi.y);
            }
            *(float4*)&redx[rr * 4] = make_float4(sum2(a0), sum2(a1), sum2(a2), sum2(a3));
        }

        // ---- warps 8-15: poll peer flag, cp.async its h chunk into h2[p^1] --
        if (t + 1 < SS && wid >= 8) {
            const int peer = wid - 8;
            if (lane == 0) {
                const unsigned* fp = &g_flag[(bg * 8 + peer) * 32];
                while (*((volatile unsigned*)fp) < (unsigned)(t + 1)) { }
            }
            __syncwarp();
            cp_async16(h2_a + (uint32_t)(((p ^ 1) * 1024 + peer * 128 + lane * 4) * 4),
                       &g_h[p ^ 1][bg * 1024 + peer * 128 + lane * 4]);
            cp_async_wait_all();
        }
        __syncthreads();                                   // sync C

        // ---- xp ring shift (redx safe: next write is after next sync A) ----
        if (do_x) {
            float nv = breg + redx[r * 4 + kq];
            xp0 = xp1; xp1 = nv;
        } else {
            xp0 = xp1;
        }
    }

    if (write_state && tid < 128) {
        const int b = tid >> 5, j = tid & 31;
        const long hoff = (long)BB * SS * HH;
        out[hoff +           (bbase + b) * HH + jbase + j] = h_last;
        out[hoff + BB * HH + (bbase + b) * HH + jbase + j] = c_reg;
    }
}

// ============================= launch ========================================
extern "C" void kernel_launch(void* const* d_in, const int* in_sizes, int n_in,
                              void* d_out, int out_size)
{
    const float* x    = (const float*)d_in[0];
    const float* W_ih = (const float*)d_in[1];
    const float* W_hh = (const float*)d_in[2];
    const float* b_ih = (const float*)d_in[3];
    const float* b_hh = (const float*)d_in[4];
    float* out = (float*)d_out;

    init_flags_kernel<<<1, 128>>>();

    cudaFuncSetAttribute(lstm_kernel,
                         cudaFuncAttributeMaxDynamicSharedMemorySize, SM_TOTAL);
    const long full = (long)BB * SS * HH + 2L * BB * HH;
    int write_state = ((long)out_size >= full) ? 1 : 0;
    lstm_kernel<<<GRID2, T2, SM_TOTAL>>>(W_hh, W_ih, b_ih, b_hh, x, out,
                                         write_state);
}